// round 9
// baseline (speedup 1.0000x reference)
#include <cuda_runtime.h>
#include <cstdint>

// ============================================================================
// AdditiveAttention fused kernels for GB300 (sm_103a) — Round 9
//   proj: BM=32, 512 threads, 2x4 microtile -> ~21 warps/SM, FFMA-saturating
//   attn: 512 threads, QT=32 (16 warps x 2 rows) -> 8 warps/SMSP, MUFU-bound
// ============================================================================

#define NEG_FILL (-1e6f)
#define S_SPLIT 8
#define QT 32
#define KT 32
#define KP 132

// Scratch (allocation-free: __device__ globals)
__device__ float g_qh[8 * 256 * 128];                 // 1 MB
__device__ float g_kh[8 * 1024 * 128];                // 4 MB
__device__ float g_po[S_SPLIT * 2048 * 128];          // 8 MB partial o
__device__ float g_pl[S_SPLIT * 2048];                // 64 KB partial l

__device__ __forceinline__ float fast_tanh(float x) {
    float y;
    asm("tanh.approx.f32 %0, %1;" : "=f"(y) : "f"(x));
    return y;
}
__device__ __forceinline__ void cp16(uint32_t s, const void* g) {
    asm volatile("cp.async.cg.shared.global [%0], [%1], 16;" :: "r"(s), "l"(g));
}
#define CP_COMMIT() asm volatile("cp.async.commit_group;")
#define CP_WAIT0()  asm volatile("cp.async.wait_group 0;")

// ----------------------------------------------------------------------------
// Projection GEMM: Y[rows,128] = X[rows,256] @ W[256,128]
// BM=32, BN=128, BK=16, 512 threads (16 warps). 2x4 microtile:
//   ty = tid>>5 (0..15) -> rows ty*2, ty*2+1 (warp-constant -> A broadcast)
//   tx = tid&31 (0..31) -> cols tx*4..+3    (conflict-free LDS.128)
// blocks 0..63 -> q rows (2048); 64..319 -> k rows (masked blocks exit).
// ----------------------------------------------------------------------------
__global__ __launch_bounds__(512) void proj_kernel(
    const float* __restrict__ Xq, const float* __restrict__ Xk,
    const float* __restrict__ Wq, const float* __restrict__ Wk,
    const int* __restrict__ valid_lens)
{
    int bx = blockIdx.x;
    const float* X; const float* W; float* Y; int row0;
    if (bx < 64) {
        X = Xq; W = Wq; Y = g_qh; row0 = bx << 5;
    } else {
        int kb = bx - 64;               // 0..255, 32 per batch
        int b  = kb >> 5;
        if (((kb & 31) << 5) >= valid_lens[b]) return;  // never read downstream
        X = Xk; W = Wk; Y = g_kh; row0 = kb << 5;
    }

    __shared__ float Xs[2][16][32];     // [buf][k][row] transposed, 4 KB
    __shared__ float Ws[2][16][128];    // [buf][k][col], 16 KB

    int tid = threadIdx.x;
    int tx = tid & 31;      // cols tx*4..+3
    int ty = tid >> 5;      // rows ty*2, ty*2+1 (== warp id)

    // load mapping: X tile 32x16 = 512 el (1 scalar/thread),
    //               W tile 16x128 = 2048 el (1 float4/thread)
    int xr = tid >> 4;              // 0..31
    int xc = tid & 15;              // 0..15
    int wr = tid >> 5;              // 0..15
    int wc = (tid & 31) << 2;       // 0..124

    const float* Xp = &X[(row0 + xr) * 256 + xc];
    const float* Wp = &W[wr * 128 + wc];

    float acc[2][4];
#pragma unroll
    for (int i = 0; i < 2; i++)
#pragma unroll
        for (int j = 0; j < 4; j++) acc[i][j] = 0.f;

    // prologue: tile 0 -> buf 0
    float  xv = *Xp;
    float4 wv = *(const float4*)Wp;
    Xs[0][xc][xr] = xv;
    *(float4*)&Ws[0][wr][wc] = wv;
    __syncthreads();

    for (int it = 0; it < 16; it++) {
        int buf = it & 1;
        if (it < 15) {  // prefetch next k-tile into registers
            int k0 = (it + 1) << 4;
            xv = *(Xp + k0);
            wv = *(const float4*)(Wp + k0 * 128);
        }
#pragma unroll
        for (int k = 0; k < 16; k++) {
            float2 a = *(float2*)&Xs[buf][k][ty * 2];   // broadcast (1 phase)
            float4 b = *(float4*)&Ws[buf][k][tx * 4];   // conflict-free
            acc[0][0] += a.x * b.x; acc[0][1] += a.x * b.y;
            acc[0][2] += a.x * b.z; acc[0][3] += a.x * b.w;
            acc[1][0] += a.y * b.x; acc[1][1] += a.y * b.y;
            acc[1][2] += a.y * b.z; acc[1][3] += a.y * b.w;
        }
        if (it < 15) {
            int nb = buf ^ 1;
            Xs[nb][xc][xr] = xv;
            *(float4*)&Ws[nb][wr][wc] = wv;
        }
        __syncthreads();
    }

#pragma unroll
    for (int i = 0; i < 2; i++) {
        int r = row0 + ty * 2 + i;
        float4 o = {acc[i][0], acc[i][1], acc[i][2], acc[i][3]};
        *(float4*)&Y[r * 128 + tx * 4] = o;
    }
}

// ----------------------------------------------------------------------------
// Split-K score + exp + AV partial kernel, cp.async double-buffered.
// grid = (Q/QT=8, B, S_SPLIT), 512 threads (16 warps, 2 q-rows per warp).
// Dynamic smem layout (floats):
//   ks[2][32][132] @ 0        (8448)
//   vs[2][32][128] @ 8448     (8192)
//   qs[32][128]    @ 16640    (4096)
//   wv[128]        @ 20736    (128)    total 20864 floats = 83456 B
// ----------------------------------------------------------------------------
#define ATTN_SMEM_BYTES 83456

__global__ __launch_bounds__(512) void attn_partial_kernel(
    const float* __restrict__ V, const int* __restrict__ valid_lens,
    const float* __restrict__ w_v)
{
    extern __shared__ float sm[];
    float* qs = sm + 16640;
    float* wv = sm + 20736;

    int b    = blockIdx.y;
    int q0   = blockIdx.x * QT;
    int sp   = blockIdx.z;
    int tid  = threadIdx.x;
    int w    = tid >> 5;
    int lane = tid & 31;
    int nv   = valid_lens[b];          // 1..1024
    int ntiles = (nv + 31) >> 5;

    uint32_t su = (uint32_t)__cvta_generic_to_shared(sm);

    // tile-load mapping: 32 rows x 16 threads, 2 x 16B chunks per thread
    int lr = tid >> 4;                 // 0..31
    int lc = (tid & 15) << 3;          // float col base (0,8,...,120)
    const float* gkb = g_kh + ((size_t)(b << 10) + lr) * 128 + lc;
    const float* gvb = V    + ((size_t)(b << 10) + lr) * 128 + lc;
    uint32_t ku0 = su + (uint32_t)(lr * KP  + lc) * 4u;
    uint32_t vu0 = su + (uint32_t)(8448 + lr * 128 + lc) * 4u;

    // prologue: issue tile sp into buf 0
    if (sp < ntiles) {
        const float* gk = gkb + (sp << 5) * 128;
        const float* gv = gvb + (sp << 5) * 128;
        cp16(ku0,        gk);
        cp16(ku0 + 16u,  gk + 4);
        cp16(vu0,        gv);
        cp16(vu0 + 16u,  gv + 4);
    }
    CP_COMMIT();

    // stage 32 q rows + w_v (overlaps with cp.async)
    {
        int r = tid >> 4;              // 0..31
        int c = (tid & 15) << 3;       // 0,8,...,120
        const float* src = &g_qh[((b << 8) + q0 + r) * 128 + c];
        *(float4*)&qs[r * 128 + c]     = *(const float4*)(src);
        *(float4*)&qs[r * 128 + c + 4] = *(const float4*)(src + 4);
    }
    if (tid < 128) wv[tid] = w_v[tid];

    float  l0 = 0.f, l1 = 0.f;
    float4 o0 = {0.f, 0.f, 0.f, 0.f};
    float4 o1 = {0.f, 0.f, 0.f, 0.f};

    const float* qsp0 = qs + (2 * w)     * 128;
    const float* qsp1 = qs + (2 * w + 1) * 128;

    int buf = 0;
    for (int t = sp; t < ntiles; t += S_SPLIT, buf ^= 1) {
        CP_WAIT0();
        __syncthreads();

        int tn = t + S_SPLIT;
        if (tn < ntiles) {
            uint32_t koff = (buf ^ 1) ? 0x4200u : 0u;   // 4224 floats * 4B
            uint32_t voff = (buf ^ 1) ? 0x4000u : 0u;   // 4096 floats * 4B
            const float* gk = gkb + (tn << 5) * 128;
            const float* gv = gvb + (tn << 5) * 128;
            cp16(ku0 + koff,       gk);
            cp16(ku0 + koff + 16u, gk + 4);
            cp16(vu0 + voff,       gv);
            cp16(vu0 + voff + 16u, gv + 4);
        }
        CP_COMMIT();

        // ---- scores for k = (t<<5) + lane, q rows 2w and 2w+1 ----
        const float* ksp = sm + buf * 4224 + lane * KP;
        float s0 = 0.f, s1 = 0.f;
#pragma unroll
        for (int h = 0; h < 128; h += 4) {
            float4 kv = *(float4*)&ksp[h];
            float4 w4 = *(float4*)&wv[h];
            float4 qa = *(float4*)&qsp0[h];
            float4 qb = *(float4*)&qsp1[h];
            s0 += fast_tanh(qa.x + kv.x) * w4.x;
            s1 += fast_tanh(qb.x + kv.x) * w4.x;
            s0 += fast_tanh(qa.y + kv.y) * w4.y;
            s1 += fast_tanh(qb.y + kv.y) * w4.y;
            s0 += fast_tanh(qa.z + kv.z) * w4.z;
            s1 += fast_tanh(qb.z + kv.z) * w4.z;
            s0 += fast_tanh(qa.w + kv.w) * w4.w;
            s1 += fast_tanh(qb.w + kv.w) * w4.w;
        }
        if ((t << 5) + lane >= nv) { s0 = NEG_FILL; s1 = NEG_FILL; }

        float p0 = __expf(s0);
        float p1 = __expf(s1);
        l0 += p0; l1 += p1;

        // ---- AV: one V read feeds both rows ----
        const float* vsp = sm + 8448 + buf * 4096;
#pragma unroll
        for (int k = 0; k < KT; k++) {
            float  pa = __shfl_sync(0xffffffffu, p0, k);
            float  pb = __shfl_sync(0xffffffffu, p1, k);
            float4 vv = *(float4*)&vsp[k * 128 + (lane << 2)];
            o0.x += pa * vv.x; o0.y += pa * vv.y;
            o0.z += pa * vv.z; o0.w += pa * vv.w;
            o1.x += pb * vv.x; o1.y += pb * vv.y;
            o1.z += pb * vv.z; o1.w += pb * vv.w;
        }
    }

#pragma unroll
    for (int off = 16; off; off >>= 1) {
        l0 += __shfl_xor_sync(0xffffffffu, l0, off);
        l1 += __shfl_xor_sync(0xffffffffu, l1, off);
    }

    int row0 = (b << 8) + q0 + 2 * w;
    if (lane == 0) {
        g_pl[sp * 2048 + row0]     = l0;
        g_pl[sp * 2048 + row0 + 1] = l1;
    }
    *(float4*)&g_po[(sp * 2048 + row0) * 128 + (lane << 2)]       = o0;
    *(float4*)&g_po[(sp * 2048 + row0 + 1) * 128 + (lane << 2)]   = o1;
}

// ----------------------------------------------------------------------------
// Combine partials: out[row,:] = sum_s o_s / sum_s l_s
// ----------------------------------------------------------------------------
__global__ __launch_bounds__(256) void combine_kernel(float* __restrict__ out)
{
    int idx = blockIdx.x * 256 + threadIdx.x;   // 0 .. 65535
    int row = idx >> 5;
    int c   = (idx & 31) << 2;

    float  l = 0.f;
    float4 a = {0.f, 0.f, 0.f, 0.f};
#pragma unroll
    for (int s = 0; s < S_SPLIT; s++) {
        l += g_pl[s * 2048 + row];
        float4 v = *(const float4*)&g_po[(s * 2048 + row) * 128 + c];
        a.x += v.x; a.y += v.y; a.z += v.z; a.w += v.w;
    }
    float inv = 1.0f / l;
    a.x *= inv; a.y *= inv; a.z *= inv; a.w *= inv;
    *(float4*)&out[row * 128 + c] = a;
}

// ----------------------------------------------------------------------------
// Launch
// ----------------------------------------------------------------------------
extern "C" void kernel_launch(void* const* d_in, const int* in_sizes, int n_in,
                              void* d_out, int out_size)
{
    const float* queries    = (const float*)d_in[0];  // [8,256,256]
    const float* keys       = (const float*)d_in[1];  // [8,1024,256]
    const float* values     = (const float*)d_in[2];  // [8,1024,128]
    const int*   valid_lens = (const int*)  d_in[3];  // [8]
    const float* W_q        = (const float*)d_in[4];  // [256,128]
    const float* W_k        = (const float*)d_in[5];  // [256,128]
    const float* w_v        = (const float*)d_in[6];  // [128]
    float*       out        = (float*)d_out;          // [8,256,128]

    cudaFuncSetAttribute(attn_partial_kernel,
                         cudaFuncAttributeMaxDynamicSharedMemorySize,
                         ATTN_SMEM_BYTES);

    proj_kernel<<<320, 512>>>(queries, keys, W_q, W_k, valid_lens);

    dim3 grid(256 / QT, 8, S_SPLIT);
    attn_partial_kernel<<<grid, 512, ATTN_SMEM_BYTES>>>(values, valid_lens, w_v);

    combine_kernel<<<256, 256>>>(out);
}

// round 10
// speedup vs baseline: 1.1486x; 1.1486x over previous
#include <cuda_runtime.h>
#include <cstdint>

// ============================================================================
// AdditiveAttention fused kernels for GB300 (sm_103a) — Round 10
//   proj: dynamic work-queue (atomic chunk counter), 16-row chunks,
//         128-thread blocks, 4x4 microtile -> per-SM FMA equalized
//   attn: R7 config (QT=16, 256 threads, split-K S=8, cp.async dbuf)
//   combine: also resets the proj chunk counter for the next graph replay
// ============================================================================

#define NEG_FILL (-1e6f)
#define S_SPLIT 8
#define QT 16
#define KT 32
#define KP 132

#define NQCHUNK 128            // 2048 q rows / 16
#define NCHUNK  640            // 128 q chunks + 512 k chunks (8192 rows / 16)

// Scratch (allocation-free: __device__ globals; zero-init at module load)
__device__ float g_qh[8 * 256 * 128];                 // 1 MB
__device__ float g_kh[8 * 1024 * 128];                // 4 MB
__device__ float g_po[S_SPLIT * 2048 * 128];          // 8 MB partial o
__device__ float g_pl[S_SPLIT * 2048];                // 64 KB partial l
__device__ int   g_ctr = 0;                           // proj work-queue head

__device__ __forceinline__ float fast_tanh(float x) {
    float y;
    asm("tanh.approx.f32 %0, %1;" : "=f"(y) : "f"(x));
    return y;
}
__device__ __forceinline__ void cp16(uint32_t s, const void* g) {
    asm volatile("cp.async.cg.shared.global [%0], [%1], 16;" :: "r"(s), "l"(g));
}
#define CP_COMMIT() asm volatile("cp.async.commit_group;")
#define CP_WAIT0()  asm volatile("cp.async.wait_group 0;")

// ----------------------------------------------------------------------------
// Projection GEMM, dynamic work queue.
// Chunk = 16 output rows x 128 cols, K=256.  chunks 0..127 -> q rows,
// 128..639 -> k rows (64 chunks per batch; masked chunks skipped).
// Block = 128 threads (4 warps), 4x4 microtile:
//   ty = tid>>5 (0..3)  -> rows ty*4..+3 (warp-constant -> A broadcast)
//   tx = tid&31 (0..31) -> cols tx*4..+3 (conflict-free LDS.128)
// Double-buffered smem (BK=16), register prefetch, 1 sync per k-tile.
// ----------------------------------------------------------------------------
__global__ __launch_bounds__(128) void proj_kernel(
    const float* __restrict__ Xq, const float* __restrict__ Xk,
    const float* __restrict__ Wq, const float* __restrict__ Wk,
    const int* __restrict__ valid_lens)
{
    __shared__ float Xs[2][16][16];     // [buf][k][row], 2 KB
    __shared__ float Ws[2][16][128];    // [buf][k][col], 16 KB
    __shared__ int   s_chunk;

    int tid = threadIdx.x;
    int tx = tid & 31;              // cols tx*4..+3
    int ty = tid >> 5;              // rows ty*4..+3 (== warp id)

    // load mapping: X tile 16x16 = 256 el -> float2/thread
    //               W tile 16x128 = 2048 el -> 4x float4/thread (rows wr+4j)
    int xr = tid >> 3;              // 0..15
    int xc = (tid & 7) << 1;        // 0..14 (even)
    int wr = tid >> 5;              // 0..3 -> W rows wr, wr+4, wr+8, wr+12
    int wc = (tid & 31) << 2;       // 0..124

    while (true) {
        if (tid == 0) s_chunk = atomicAdd(&g_ctr, 1);
        __syncthreads();
        int c = s_chunk;
        __syncthreads();            // all read s_chunk before next overwrite
        if (c >= NCHUNK) return;

        const float* X; const float* W; float* Y; int row0;
        if (c < NQCHUNK) {
            X = Xq; W = Wq; Y = g_qh; row0 = c << 4;
        } else {
            int kc = c - NQCHUNK;           // 0..511, 64 per batch
            int b  = kc >> 6;
            int local = (kc & 63) << 4;
            if (local >= valid_lens[b]) continue;   // rows never read downstream
            X = Xk; W = Wk; Y = g_kh; row0 = (b << 10) + local;
        }

        const float* Xp  = &X[(row0 + xr) * 256 + xc];
        const float* Wp0 = &W[(wr)      * 128 + wc];
        const float* Wp1 = &W[(wr + 4)  * 128 + wc];
        const float* Wp2 = &W[(wr + 8)  * 128 + wc];
        const float* Wp3 = &W[(wr + 12) * 128 + wc];

        float acc[4][4];
#pragma unroll
        for (int i = 0; i < 4; i++)
#pragma unroll
            for (int j = 0; j < 4; j++) acc[i][j] = 0.f;

        // prologue: k-tile 0 -> buf 0
        float2 xv  = *(const float2*)Xp;
        float4 wv0 = *(const float4*)Wp0;
        float4 wv1 = *(const float4*)Wp1;
        float4 wv2 = *(const float4*)Wp2;
        float4 wv3 = *(const float4*)Wp3;
        Xs[0][xc][xr] = xv.x; Xs[0][xc + 1][xr] = xv.y;
        *(float4*)&Ws[0][wr][wc]      = wv0;
        *(float4*)&Ws[0][wr + 4][wc]  = wv1;
        *(float4*)&Ws[0][wr + 8][wc]  = wv2;
        *(float4*)&Ws[0][wr + 12][wc] = wv3;
        __syncthreads();

        for (int it = 0; it < 16; it++) {
            int buf = it & 1;
            if (it < 15) {  // prefetch next k-tile into registers
                int k0 = (it + 1) << 4;
                xv  = *(const float2*)(Xp + k0);
                wv0 = *(const float4*)(Wp0 + k0 * 128);
                wv1 = *(const float4*)(Wp1 + k0 * 128);
                wv2 = *(const float4*)(Wp2 + k0 * 128);
                wv3 = *(const float4*)(Wp3 + k0 * 128);
            }
#pragma unroll
            for (int k = 0; k < 16; k++) {
                float4 a = *(float4*)&Xs[buf][k][ty * 4];   // broadcast
                float4 b = *(float4*)&Ws[buf][k][tx * 4];   // conflict-free
                float av[4] = {a.x, a.y, a.z, a.w};
                float bv[4] = {b.x, b.y, b.z, b.w};
#pragma unroll
                for (int i = 0; i < 4; i++)
#pragma unroll
                    for (int j = 0; j < 4; j++)
                        acc[i][j] += av[i] * bv[j];
            }
            if (it < 15) {
                int nb = buf ^ 1;
                Xs[nb][xc][xr] = xv.x; Xs[nb][xc + 1][xr] = xv.y;
                *(float4*)&Ws[nb][wr][wc]      = wv0;
                *(float4*)&Ws[nb][wr + 4][wc]  = wv1;
                *(float4*)&Ws[nb][wr + 8][wc]  = wv2;
                *(float4*)&Ws[nb][wr + 12][wc] = wv3;
            }
            __syncthreads();
        }

#pragma unroll
        for (int i = 0; i < 4; i++) {
            int r = row0 + ty * 4 + i;
            float4 o = {acc[i][0], acc[i][1], acc[i][2], acc[i][3]};
            *(float4*)&Y[r * 128 + tx * 4] = o;
        }
        // epilogue stores are to distinct addresses per chunk; no sync needed
        // before the next pull (s_chunk protected by the two syncs at top)
    }
}

// ----------------------------------------------------------------------------
// Split-K score + exp + AV partial kernel, cp.async double-buffered.
// grid = (Q/QT=16, B, S_SPLIT), 256 threads, 8 warps, 2 q-rows per warp.
// Dynamic smem layout (floats):
//   ks[2][32][132] @ 0        (8448)
//   vs[2][32][128] @ 8448     (8192)
//   qs[16][128]    @ 16640    (2048)
//   wv[128]        @ 18688    (128)    total 18816 floats = 75264 B
// ----------------------------------------------------------------------------
#define ATTN_SMEM_BYTES 75264

__global__ __launch_bounds__(256) void attn_partial_kernel(
    const float* __restrict__ V, const int* __restrict__ valid_lens,
    const float* __restrict__ w_v)
{
    extern __shared__ float sm[];
    float* qs = sm + 16640;
    float* wv = sm + 18688;

    int b    = blockIdx.y;
    int q0   = blockIdx.x * QT;
    int sp   = blockIdx.z;
    int tid  = threadIdx.x;
    int w    = tid >> 5;
    int lane = tid & 31;
    int nv   = valid_lens[b];          // 1..1024
    int ntiles = (nv + 31) >> 5;

    uint32_t su = (uint32_t)__cvta_generic_to_shared(sm);

    int lr = tid >> 3;                 // 0..31
    int lc = (tid & 7) << 2;           // float col base
    const float* gkb = g_kh + ((size_t)(b << 10) + lr) * 128 + lc;
    const float* gvb = V    + ((size_t)(b << 10) + lr) * 128 + lc;
    uint32_t ku0 = su + (uint32_t)(lr * KP  + lc) * 4u;
    uint32_t vu0 = su + (uint32_t)(8448 + lr * 128 + lc) * 4u;

    // prologue: issue tile sp into buf 0
    if (sp < ntiles) {
        const float* gk = gkb + (sp << 5) * 128;
        const float* gv = gvb + (sp << 5) * 128;
#pragma unroll
        for (int j = 0; j < 4; j++) {
            cp16(ku0 + j * 128u, gk + (j << 3) * 4);
            cp16(vu0 + j * 128u, gv + (j << 3) * 4);
        }
    }
    CP_COMMIT();

    // stage 16 q rows + w_v (overlaps with cp.async)
    {
        int r = tid >> 4;              // 0..15
        int c = (tid & 15) << 3;       // 0,8,...,120
        const float* src = &g_qh[((b << 8) + q0 + r) * 128 + c];
        *(float4*)&qs[r * 128 + c]     = *(const float4*)(src);
        *(float4*)&qs[r * 128 + c + 4] = *(const float4*)(src + 4);
    }
    if (tid < 128) wv[tid] = w_v[tid];

    float  l0 = 0.f, l1 = 0.f;
    float4 o0 = {0.f, 0.f, 0.f, 0.f};
    float4 o1 = {0.f, 0.f, 0.f, 0.f};

    const float* qsp0 = qs + (2 * w)     * 128;
    const float* qsp1 = qs + (2 * w + 1) * 128;

    int buf = 0;
    for (int t = sp; t < ntiles; t += S_SPLIT, buf ^= 1) {
        CP_WAIT0();
        __syncthreads();

        int tn = t + S_SPLIT;
        if (tn < ntiles) {
            uint32_t koff = (buf ^ 1) ? 0x4200u : 0u;   // 4224 floats * 4B
            uint32_t voff = (buf ^ 1) ? 0x4000u : 0u;   // 4096 floats * 4B
            const float* gk = gkb + (tn << 5) * 128;
            const float* gv = gvb + (tn << 5) * 128;
#pragma unroll
            for (int j = 0; j < 4; j++) {
                cp16(ku0 + koff + j * 128u, gk + (j << 3) * 4);
                cp16(vu0 + voff + j * 128u, gv + (j << 3) * 4);
            }
        }
        CP_COMMIT();

        // ---- scores for k = (t<<5) + lane, q rows 2w and 2w+1 ----
        const float* ksp = sm + buf * 4224 + lane * KP;
        float s0 = 0.f, s1 = 0.f;
#pragma unroll
        for (int h = 0; h < 128; h += 4) {
            float4 kv = *(float4*)&ksp[h];
            float4 w4 = *(float4*)&wv[h];
            float4 qa = *(float4*)&qsp0[h];
            float4 qb = *(float4*)&qsp1[h];
            s0 += fast_tanh(qa.x + kv.x) * w4.x;
            s1 += fast_tanh(qb.x + kv.x) * w4.x;
            s0 += fast_tanh(qa.y + kv.y) * w4.y;
            s1 += fast_tanh(qb.y + kv.y) * w4.y;
            s0 += fast_tanh(qa.z + kv.z) * w4.z;
            s1 += fast_tanh(qb.z + kv.z) * w4.z;
            s0 += fast_tanh(qa.w + kv.w) * w4.w;
            s1 += fast_tanh(qb.w + kv.w) * w4.w;
        }
        if ((t << 5) + lane >= nv) { s0 = NEG_FILL; s1 = NEG_FILL; }

        float p0 = __expf(s0);
        float p1 = __expf(s1);
        l0 += p0; l1 += p1;

        // ---- AV: one V read feeds both rows ----
        const float* vsp = sm + 8448 + buf * 4096;
#pragma unroll
        for (int k = 0; k < KT; k++) {
            float  pa = __shfl_sync(0xffffffffu, p0, k);
            float  pb = __shfl_sync(0xffffffffu, p1, k);
            float4 vv = *(float4*)&vsp[k * 128 + (lane << 2)];
            o0.x += pa * vv.x; o0.y += pa * vv.y;
            o0.z += pa * vv.z; o0.w += pa * vv.w;
            o1.x += pb * vv.x; o1.y += pb * vv.y;
            o1.z += pb * vv.z; o1.w += pb * vv.w;
        }
    }

#pragma unroll
    for (int off = 16; off; off >>= 1) {
        l0 += __shfl_xor_sync(0xffffffffu, l0, off);
        l1 += __shfl_xor_sync(0xffffffffu, l1, off);
    }

    int row0 = (b << 8) + q0 + 2 * w;
    if (lane == 0) {
        g_pl[sp * 2048 + row0]     = l0;
        g_pl[sp * 2048 + row0 + 1] = l1;
    }
    *(float4*)&g_po[(sp * 2048 + row0) * 128 + (lane << 2)]       = o0;
    *(float4*)&g_po[(sp * 2048 + row0 + 1) * 128 + (lane << 2)]   = o1;
}

// ----------------------------------------------------------------------------
// Combine partials: out[row,:] = sum_s o_s / sum_s l_s.
// Also resets the proj work-queue counter for the next graph replay.
// ----------------------------------------------------------------------------
__global__ __launch_bounds__(256) void combine_kernel(float* __restrict__ out)
{
    if (blockIdx.x == 0 && threadIdx.x == 0) g_ctr = 0;   // queue reset

    int idx = blockIdx.x * 256 + threadIdx.x;   // 0 .. 65535
    int row = idx >> 5;
    int c   = (idx & 31) << 2;

    float  l = 0.f;
    float4 a = {0.f, 0.f, 0.f, 0.f};
#pragma unroll
    for (int s = 0; s < S_SPLIT; s++) {
        l += g_pl[s * 2048 + row];
        float4 v = *(const float4*)&g_po[(s * 2048 + row) * 128 + c];
        a.x += v.x; a.y += v.y; a.z += v.z; a.w += v.w;
    }
    float inv = 1.0f / l;
    a.x *= inv; a.y *= inv; a.z *= inv; a.w *= inv;
    *(float4*)&out[row * 128 + c] = a;
}

// ----------------------------------------------------------------------------
// Launch
// ----------------------------------------------------------------------------
extern "C" void kernel_launch(void* const* d_in, const int* in_sizes, int n_in,
                              void* d_out, int out_size)
{
    const float* queries    = (const float*)d_in[0];  // [8,256,256]
    const float* keys       = (const float*)d_in[1];  // [8,1024,256]
    const float* values     = (const float*)d_in[2];  // [8,1024,128]
    const int*   valid_lens = (const int*)  d_in[3];  // [8]
    const float* W_q        = (const float*)d_in[4];  // [256,128]
    const float* W_k        = (const float*)d_in[5];  // [256,128]
    const float* w_v        = (const float*)d_in[6];  // [128]
    float*       out        = (float*)d_out;          // [8,256,128]

    cudaFuncSetAttribute(attn_partial_kernel,
                         cudaFuncAttributeMaxDynamicSharedMemorySize,
                         ATTN_SMEM_BYTES);

    // 592 worker blocks (~4/SM), each pulls 16-row chunks until queue empty
    proj_kernel<<<592, 128>>>(queries, keys, W_q, W_k, valid_lens);

    dim3 grid(256 / QT, 8, S_SPLIT);
    attn_partial_kernel<<<grid, 256, ATTN_SMEM_BYTES>>>(values, valid_lens, w_v);

    combine_kernel<<<256, 256>>>(out);
}

// round 12
// speedup vs baseline: 1.4219x; 1.2379x over previous
#include <cuda_runtime.h>
#include <cstdint>

// ============================================================================
// AdditiveAttention fused kernels for GB300 (sm_103a) — Round 11
//   proj: work-queue (atomic 32-row chunks) x R8 block shape
//         (256 thr, 8 warps, 4x4 microtile, 20KB smem, 2-3 blocks/SM)
//   attn: R7 config + smem-broadcast AV (no shfl)
// ============================================================================

#define NEG_FILL (-1e6f)
#define S_SPLIT 8
#define QT 16
#define KT 32
#define KP 132

#define NQCHUNK 64             // 2048 q rows / 32
#define NCHUNK  320            // 64 q chunks + 256 k chunks (8192 rows / 32)

// Scratch (allocation-free: __device__ globals; zero-init at module load)
__device__ float g_qh[8 * 256 * 128];                 // 1 MB
__device__ float g_kh[8 * 1024 * 128];                // 4 MB
__device__ float g_po[S_SPLIT * 2048 * 128];          // 8 MB partial o
__device__ float g_pl[S_SPLIT * 2048];                // 64 KB partial l
__device__ int   g_ctr = 0;                           // proj work-queue head

__device__ __forceinline__ float fast_tanh(float x) {
    float y;
    asm("tanh.approx.f32 %0, %1;" : "=f"(y) : "f"(x));
    return y;
}
__device__ __forceinline__ void cp16(uint32_t s, const void* g) {
    asm volatile("cp.async.cg.shared.global [%0], [%1], 16;" :: "r"(s), "l"(g));
}
#define CP_COMMIT() asm volatile("cp.async.commit_group;")
#define CP_WAIT0()  asm volatile("cp.async.wait_group 0;")

// ----------------------------------------------------------------------------
// Projection GEMM, dynamic work queue.
// Chunk = 32 output rows x 128 cols, K=256.  chunks 0..63 -> q rows,
// 64..319 -> k rows (32 chunks per batch; masked chunks skipped in ~1 pull).
// Block = 256 threads (8 warps), 4x4 microtile:
//   ty = tid>>5 (0..7)  -> rows ty*4..+3 (warp-constant -> A broadcast)
//   tx = tid&31 (0..31) -> cols tx*4..+3 (conflict-free LDS.128)
// Double-buffered smem (BK=16), register prefetch, 1 sync per k-tile.
// ----------------------------------------------------------------------------
__global__ __launch_bounds__(256) void proj_kernel(
    const float* __restrict__ Xq, const float* __restrict__ Xk,
    const float* __restrict__ Wq, const float* __restrict__ Wk,
    const int* __restrict__ valid_lens)
{
    __shared__ float Xs[2][16][32];     // [buf][k][row], 4 KB
    __shared__ float Ws[2][16][128];    // [buf][k][col], 16 KB
    __shared__ int   s_chunk;

    int tid = threadIdx.x;
    int tx = tid & 31;              // cols tx*4..+3
    int ty = tid >> 5;              // rows ty*4..+3 (== warp id)

    // load mapping: X tile 32x16 = 512 el -> float2/thread
    //               W tile 16x128 = 2048 el -> 2x float4/thread (rows wr, wr+8)
    int xr = tid >> 3;              // 0..31
    int xc = (tid & 7) << 1;        // 0..14 (even)
    int wr = tid >> 5;              // 0..7
    int wc = (tid & 31) << 2;       // 0..124

    while (true) {
        if (tid == 0) s_chunk = atomicAdd(&g_ctr, 1);
        __syncthreads();
        int c = s_chunk;
        __syncthreads();            // all read s_chunk before next overwrite
        if (c >= NCHUNK) return;

        const float* X; const float* W; float* Y; int row0;
        if (c < NQCHUNK) {
            X = Xq; W = Wq; Y = g_qh; row0 = c << 5;
        } else {
            int kc = c - NQCHUNK;           // 0..255, 32 per batch
            int b  = kc >> 5;
            if (((kc & 31) << 5) >= valid_lens[b]) continue;  // never read
            X = Xk; W = Wk; Y = g_kh; row0 = kc << 5;
        }

        const float* Xp  = &X[(row0 + xr) * 256 + xc];
        const float* Wp0 = &W[wr * 128 + wc];
        const float* Wp1 = &W[(wr + 8) * 128 + wc];

        float acc[4][4];
#pragma unroll
        for (int i = 0; i < 4; i++)
#pragma unroll
            for (int j = 0; j < 4; j++) acc[i][j] = 0.f;

        // prologue: k-tile 0 -> buf 0
        float2 xv  = *(const float2*)Xp;
        float4 wv0 = *(const float4*)Wp0;
        float4 wv1 = *(const float4*)Wp1;
        Xs[0][xc][xr] = xv.x; Xs[0][xc + 1][xr] = xv.y;
        *(float4*)&Ws[0][wr][wc]     = wv0;
        *(float4*)&Ws[0][wr + 8][wc] = wv1;
        __syncthreads();

        for (int it = 0; it < 16; it++) {
            int buf = it & 1;
            if (it < 15) {  // prefetch next k-tile into registers
                int k0 = (it + 1) << 4;
                xv  = *(const float2*)(Xp + k0);
                wv0 = *(const float4*)(Wp0 + k0 * 128);
                wv1 = *(const float4*)(Wp1 + k0 * 128);
            }
#pragma unroll
            for (int k = 0; k < 16; k++) {
                float4 a = *(float4*)&Xs[buf][k][ty * 4];   // broadcast
                float4 b = *(float4*)&Ws[buf][k][tx * 4];   // conflict-free
                float av[4] = {a.x, a.y, a.z, a.w};
                float bv[4] = {b.x, b.y, b.z, b.w};
#pragma unroll
                for (int i = 0; i < 4; i++)
#pragma unroll
                    for (int j = 0; j < 4; j++)
                        acc[i][j] += av[i] * bv[j];
            }
            if (it < 15) {
                int nb = buf ^ 1;
                Xs[nb][xc][xr] = xv.x; Xs[nb][xc + 1][xr] = xv.y;
                *(float4*)&Ws[nb][wr][wc]     = wv0;
                *(float4*)&Ws[nb][wr + 8][wc] = wv1;
            }
            __syncthreads();
        }

#pragma unroll
        for (int i = 0; i < 4; i++) {
            int r = row0 + ty * 4 + i;
            float4 o = {acc[i][0], acc[i][1], acc[i][2], acc[i][3]};
            *(float4*)&Y[r * 128 + tx * 4] = o;
        }
        // stores hit distinct addresses per chunk; the two syncs at loop top
        // protect s_chunk reuse
    }
}

// ----------------------------------------------------------------------------
// Split-K score + exp + AV partial kernel, cp.async double-buffered.
// grid = (Q/QT=16, B, S_SPLIT), 256 threads, 8 warps, 2 q-rows per warp.
// AV uses a per-warp smem p-strip with float4 broadcast reads (no shfl).
// Dynamic smem layout (floats):
//   ks[2][32][132] @ 0        (8448)
//   vs[2][32][128] @ 8448     (8192)
//   qs[16][128]    @ 16640    (2048)
//   wv[128]        @ 18688    (128)
//   pb[8][2][32]   @ 18816    (512)    total 19328 floats = 77312 B
// ----------------------------------------------------------------------------
#define ATTN_SMEM_BYTES 77312

__global__ __launch_bounds__(256) void attn_partial_kernel(
    const float* __restrict__ V, const int* __restrict__ valid_lens,
    const float* __restrict__ w_v)
{
    extern __shared__ float sm[];
    float* qs = sm + 16640;
    float* wv = sm + 18688;
    float* pb = sm + 18816;

    int b    = blockIdx.y;
    int q0   = blockIdx.x * QT;
    int sp   = blockIdx.z;
    int tid  = threadIdx.x;
    int w    = tid >> 5;
    int lane = tid & 31;
    int nv   = valid_lens[b];          // 1..1024
    int ntiles = (nv + 31) >> 5;

    uint32_t su = (uint32_t)__cvta_generic_to_shared(sm);

    int lr = tid >> 3;                 // 0..31
    int lc = (tid & 7) << 2;           // float col base
    const float* gkb = g_kh + ((size_t)(b << 10) + lr) * 128 + lc;
    const float* gvb = V    + ((size_t)(b << 10) + lr) * 128 + lc;
    uint32_t ku0 = su + (uint32_t)(lr * KP  + lc) * 4u;
    uint32_t vu0 = su + (uint32_t)(8448 + lr * 128 + lc) * 4u;

    // prologue: issue tile sp into buf 0
    if (sp < ntiles) {
        const float* gk = gkb + (sp << 5) * 128;
        const float* gv = gvb + (sp << 5) * 128;
#pragma unroll
        for (int j = 0; j < 4; j++) {
            cp16(ku0 + j * 128u, gk + (j << 3) * 4);
            cp16(vu0 + j * 128u, gv + (j << 3) * 4);
        }
    }
    CP_COMMIT();

    // stage 16 q rows + w_v (overlaps with cp.async)
    {
        int r = tid >> 4;              // 0..15
        int c = (tid & 15) << 3;       // 0,8,...,120
        const float* src = &g_qh[((b << 8) + q0 + r) * 128 + c];
        *(float4*)&qs[r * 128 + c]     = *(const float4*)(src);
        *(float4*)&qs[r * 128 + c + 4] = *(const float4*)(src + 4);
    }
    if (tid < 128) wv[tid] = w_v[tid];

    float  l0 = 0.f, l1 = 0.f;
    float4 o0 = {0.f, 0.f, 0.f, 0.f};
    float4 o1 = {0.f, 0.f, 0.f, 0.f};

    const float* qsp0 = qs + (2 * w)     * 128;
    const float* qsp1 = qs + (2 * w + 1) * 128;
    float* pw = pb + w * 64;           // [2][32] strip for this warp

    int buf = 0;
    for (int t = sp; t < ntiles; t += S_SPLIT, buf ^= 1) {
        CP_WAIT0();
        __syncthreads();

        int tn = t + S_SPLIT;
        if (tn < ntiles) {
            uint32_t koff = (buf ^ 1) ? 0x4200u : 0u;   // 4224 floats * 4B
            uint32_t voff = (buf ^ 1) ? 0x4000u : 0u;   // 4096 floats * 4B
            const float* gk = gkb + (tn << 5) * 128;
            const float* gv = gvb + (tn << 5) * 128;
#pragma unroll
            for (int j = 0; j < 4; j++) {
                cp16(ku0 + koff + j * 128u, gk + (j << 3) * 4);
                cp16(vu0 + voff + j * 128u, gv + (j << 3) * 4);
            }
        }
        CP_COMMIT();

        // ---- scores for k = (t<<5) + lane, q rows 2w and 2w+1 ----
        const float* ksp = sm + buf * 4224 + lane * KP;
        float s0 = 0.f, s1 = 0.f;
#pragma unroll
        for (int h = 0; h < 128; h += 4) {
            float4 kv = *(float4*)&ksp[h];
            float4 w4 = *(float4*)&wv[h];
            float4 qa = *(float4*)&qsp0[h];
            float4 qb = *(float4*)&qsp1[h];
            s0 += fast_tanh(qa.x + kv.x) * w4.x;
            s1 += fast_tanh(qb.x + kv.x) * w4.x;
            s0 += fast_tanh(qa.y + kv.y) * w4.y;
            s1 += fast_tanh(qb.y + kv.y) * w4.y;
            s0 += fast_tanh(qa.z + kv.z) * w4.z;
            s1 += fast_tanh(qb.z + kv.z) * w4.z;
            s0 += fast_tanh(qa.w + kv.w) * w4.w;
            s1 += fast_tanh(qb.w + kv.w) * w4.w;
        }
        if ((t << 5) + lane >= nv) { s0 = NEG_FILL; s1 = NEG_FILL; }

        float p0 = __expf(s0);
        float p1 = __expf(s1);
        l0 += p0; l1 += p1;

        // publish p to the warp strip, then broadcast-read as float4
        pw[lane]      = p0;
        pw[32 + lane] = p1;
        __syncwarp();

        // ---- AV: one V read + one p4 pair per 4 k-steps ----
        const float* vsp = sm + 8448 + buf * 4096 + (lane << 2);
#pragma unroll
        for (int g = 0; g < 8; g++) {
            float4 pa = *(float4*)&pw[g * 4];
            float4 pc = *(float4*)&pw[32 + g * 4];
            float4 v0 = *(float4*)&vsp[(g * 4 + 0) * 128];
            float4 v1 = *(float4*)&vsp[(g * 4 + 1) * 128];
            float4 v2 = *(float4*)&vsp[(g * 4 + 2) * 128];
            float4 v3 = *(float4*)&vsp[(g * 4 + 3) * 128];
            o0.x += pa.x * v0.x; o0.y += pa.x * v0.y;
            o0.z += pa.x * v0.z; o0.w += pa.x * v0.w;
            o1.x += pc.x * v0.x; o1.y += pc.x * v0.y;
            o1.z += pc.x * v0.z; o1.w += pc.x * v0.w;
            o0.x += pa.y * v1.x; o0.y += pa.y * v1.y;
            o0.z += pa.y * v1.z; o0.w += pa.y * v1.w;
            o1.x += pc.y * v1.x; o1.y += pc.y * v1.y;
            o1.z += pc.y * v1.z; o1.w += pc.y * v1.w;
            o0.x += pa.z * v2.x; o0.y += pa.z * v2.y;
            o0.z += pa.z * v2.z; o0.w += pa.z * v2.w;
            o1.x += pc.z * v2.x; o1.y += pc.z * v2.y;
            o1.z += pc.z * v2.z; o1.w += pc.z * v2.w;
            o0.x += pa.w * v3.x; o0.y += pa.w * v3.y;
            o0.z += pa.w * v3.z; o0.w += pa.w * v3.w;
            o1.x += pc.w * v3.x; o1.y += pc.w * v3.y;
            o1.z += pc.w * v3.z; o1.w += pc.w * v3.w;
        }
    }

#pragma unroll
    for (int off = 16; off; off >>= 1) {
        l0 += __shfl_xor_sync(0xffffffffu, l0, off);
        l1 += __shfl_xor_sync(0xffffffffu, l1, off);
    }

    int row0 = (b << 8) + q0 + 2 * w;
    if (lane == 0) {
        g_pl[sp * 2048 + row0]     = l0;
        g_pl[sp * 2048 + row0 + 1] = l1;
    }
    *(float4*)&g_po[(sp * 2048 + row0) * 128 + (lane << 2)]       = o0;
    *(float4*)&g_po[(sp * 2048 + row0 + 1) * 128 + (lane << 2)]   = o1;
}

// ----------------------------------------------------------------------------
// Combine partials: out[row,:] = sum_s o_s / sum_s l_s.
// Also resets the proj work-queue counter for the next graph replay.
// ----------------------------------------------------------------------------
__global__ __launch_bounds__(256) void combine_kernel(float* __restrict__ out)
{
    if (blockIdx.x == 0 && threadIdx.x == 0) g_ctr = 0;   // queue reset

    int idx = blockIdx.x * 256 + threadIdx.x;   // 0 .. 65535
    int row = idx >> 5;
    int c   = (idx & 31) << 2;

    float  l = 0.f;
    float4 a = {0.f, 0.f, 0.f, 0.f};
#pragma unroll
    for (int s = 0; s < S_SPLIT; s++) {
        l += g_pl[s * 2048 + row];
        float4 v = *(const float4*)&g_po[(s * 2048 + row) * 128 + c];
        a.x += v.x; a.y += v.y; a.z += v.z; a.w += v.w;
    }
    float inv = 1.0f / l;
    a.x *= inv; a.y *= inv; a.z *= inv; a.w *= inv;
    *(float4*)&out[row * 128 + c] = a;
}

// ----------------------------------------------------------------------------
// Launch
// ----------------------------------------------------------------------------
extern "C" void kernel_launch(void* const* d_in, const int* in_sizes, int n_in,
                              void* d_out, int out_size)
{
    const float* queries    = (const float*)d_in[0];  // [8,256,256]
    const float* keys       = (const float*)d_in[1];  // [8,1024,256]
    const float* values     = (const float*)d_in[2];  // [8,1024,128]
    const int*   valid_lens = (const int*)  d_in[3];  // [8]
    const float* W_q        = (const float*)d_in[4];  // [256,128]
    const float* W_k        = (const float*)d_in[5];  // [256,128]
    const float* w_v        = (const float*)d_in[6];  // [128]
    float*       out        = (float*)d_out;          // [8,256,128]

    cudaFuncSetAttribute(attn_partial_kernel,
                         cudaFuncAttributeMaxDynamicSharedMemorySize,
                         ATTN_SMEM_BYTES);

    // 296 worker blocks (2/SM), each pulls 32-row chunks until queue empty
    proj_kernel<<<296, 256>>>(queries, keys, W_q, W_k, valid_lens);

    dim3 grid(256 / QT, 8, S_SPLIT);
    attn_partial_kernel<<<grid, 256, ATTN_SMEM_BYTES>>>(values, valid_lens, w_v);

    combine_kernel<<<256, 256>>>(out);
}